// round 4
// baseline (speedup 1.0000x reference)
#include <cuda_runtime.h>
#include <cuda_fp16.h>
#include <cstdint>

// ---------------- problem constants ----------------
#define Bb    32
#define Tt    128
#define Pp    512
#define MAXL  7
#define Dd    300
#define KSEG  320            // per-segment K (>=300, 3*KSEG % 32 == 0)
#define KP    (3*KSEG)       // 960 = 30*32
#define Nn    7168           // P*ND*MAXL
#define Mm    4096           // B*T
#define NCc   2
#define NEGV  (-1e30f)

// gemm tiling
#define BK    32
#define NKT   (KP/BK)        // 30
#define NSTG  4
#define ROWB  80             // smem row stride bytes (64 data + 16 pad -> conflict-free ldmatrix)
#define STAGE_A   (128*ROWB)        // 10240
#define STAGE_SZ  (2*STAGE_A)       // 20480 (A then B)
#define SMEM_GEMM (NSTG*STAGE_SZ)   // 81920

// ---------------- scratch ----------------
__device__ __half g_Aq[(size_t)Mm * KP];   // [h,h,m]
__device__ __half g_Bq[(size_t)Nn * KP];   // [h,m,h]
__device__ float g_ts[(size_t)Mm * Nn];    // 117 MB
__device__ float g_scores[Bb * Pp];

// ---------------- PTX helpers ----------------
__device__ __forceinline__ void cpasync16(uint32_t s, const void* g){
    asm volatile("cp.async.cg.shared.global [%0], [%1], 16;" :: "r"(s), "l"(g));
}
__device__ __forceinline__ void cp_commit(){
    asm volatile("cp.async.commit_group;" ::: "memory");
}
template<int N> __device__ __forceinline__ void cp_wait(){
    asm volatile("cp.async.wait_group %0;" :: "n"(N) : "memory");
}
__device__ __forceinline__ void ldsm4(uint32_t a, uint32_t& r0, uint32_t& r1, uint32_t& r2, uint32_t& r3){
    asm volatile("ldmatrix.sync.aligned.m8n8.x4.shared.b16 {%0,%1,%2,%3}, [%4];"
                 : "=r"(r0), "=r"(r1), "=r"(r2), "=r"(r3) : "r"(a));
}
__device__ __forceinline__ void mma16816(float* c, uint32_t a0, uint32_t a1, uint32_t a2, uint32_t a3,
                                         uint32_t b0, uint32_t b1){
    asm volatile("mma.sync.aligned.m16n8k16.row.col.f32.f16.f16.f32 "
                 "{%0,%1,%2,%3}, {%4,%5,%6,%7}, {%8,%9}, {%0,%1,%2,%3};"
                 : "+f"(c[0]), "+f"(c[1]), "+f"(c[2]), "+f"(c[3])
                 : "r"(a0), "r"(a1), "r"(a2), "r"(a3), "r"(b0), "r"(b1));
}

// ---------------- 1/2. fp16 split-precision conversion ----------------
__global__ void convA_kernel(const int* __restrict__ tokens, const float* __restrict__ emb){
    int mrow = blockIdx.x;
    int tok = tokens[mrow];
    __half* row = g_Aq + (size_t)mrow * KP;
    const float* src = emb + (size_t)tok * Dd;
    for (int k = threadIdx.x; k < KSEG; k += blockDim.x){
        float x = (k < Dd) ? src[k] : 0.0f;
        __half h = __float2half(x);
        __half m = __float2half(x - __half2float(h));
        row[0*KSEG + k] = h;  row[1*KSEG + k] = h;  row[2*KSEG + k] = m;
    }
}
__global__ void convB_kernel(const float* __restrict__ diags){
    int n = blockIdx.x;
    __half* row = g_Bq + (size_t)n * KP;
    const float* src = diags + (size_t)n * Dd;
    for (int k = threadIdx.x; k < KSEG; k += blockDim.x){
        float x = (k < Dd) ? src[k] : 0.0f;
        __half h = __float2half(x);
        __half m = __float2half(x - __half2float(h));
        row[0*KSEG + k] = h;  row[1*KSEG + k] = m;  row[2*KSEG + k] = h;
    }
}

// ---------------- 3. fp16 mma.sync GEMM: ts[m][n] = sum_k A'[m][k]*B'[n][k] + bias[n] ----------------
// CTA 128x128, BK=32, 256 threads = 8 warps (2 M x 4 N), warp tile 64x32.
__global__ __launch_bounds__(256, 2) void gemm_kernel(const float* __restrict__ bias)
{
    extern __shared__ char smem[];
    const uint32_t sb = (uint32_t)__cvta_generic_to_shared(smem);
    const int tid = threadIdx.x;
    const int lane = tid & 31, wid = tid >> 5;
    const int wm = wid & 1, wn = wid >> 1;
    const int blockM = blockIdx.y * 128;
    const int blockN = blockIdx.x * 128;

    const __half* gA = g_Aq + (size_t)blockM * KP;
    const __half* gB = g_Bq + (size_t)blockN * KP;

    // cp.async assignment: each thread loads one 32B run of one row (A and B)
    const int ldRow = tid >> 1;            // 0..127
    const int ldCh  = (tid & 1) * 2;       // chunk base 0 or 2 (16B chunks)
    const uint32_t sA_off = ldRow * ROWB + ldCh * 16;
    const size_t   gOff   = (size_t)ldRow * KP + ldCh * 8;   // elements

    // ldmatrix source addresses (per-lane)
    const uint32_t aBase = sb + (wm*64 + (lane & 15)) * ROWB + (lane >> 4) * 16;
    const uint32_t bBase = sb + STAGE_A + (wn*32 + ((lane >> 4) << 3) + (lane & 7)) * ROWB
                              + (((lane >> 3) & 1) * 16);

    float acc[4][4][4];
    #pragma unroll
    for (int i = 0; i < 4; i++)
        #pragma unroll
        for (int j = 0; j < 4; j++)
            #pragma unroll
            for (int r = 0; r < 4; r++) acc[i][j][r] = 0.0f;

    // prologue: load stages 0..NSTG-2
    #pragma unroll
    for (int s = 0; s < NSTG-1; s++){
        uint32_t st = sb + s*STAGE_SZ + sA_off;
        const __half* pa = gA + gOff + s*BK;
        const __half* pb = gB + gOff + s*BK;
        cpasync16(st,            pa);
        cpasync16(st + 16,       pa + 8);
        cpasync16(st + STAGE_A,      pb);
        cpasync16(st + STAGE_A + 16, pb + 8);
        cp_commit();
    }

    for (int kt = 0; kt < NKT; kt++){
        cp_wait<NSTG-2>();
        __syncthreads();

        int nkt = kt + NSTG - 1;
        if (nkt < NKT){
            uint32_t st = sb + (nkt % NSTG)*STAGE_SZ + sA_off;
            const __half* pa = gA + gOff + nkt*BK;
            const __half* pb = gB + gOff + nkt*BK;
            cpasync16(st,            pa);
            cpasync16(st + 16,       pa + 8);
            cpasync16(st + STAGE_A,      pb);
            cpasync16(st + STAGE_A + 16, pb + 8);
        }
        cp_commit();

        const uint32_t stage = (kt % NSTG) * STAGE_SZ;
        #pragma unroll
        for (int s = 0; s < 2; s++){
            uint32_t a[4][4], b[4][2];
            #pragma unroll
            for (int i = 0; i < 4; i++)
                ldsm4(aBase + stage + i*16*ROWB + s*32, a[i][0], a[i][1], a[i][2], a[i][3]);
            #pragma unroll
            for (int j2 = 0; j2 < 2; j2++){
                uint32_t r0, r1, r2, r3;
                ldsm4(bBase + stage + j2*16*ROWB + s*32, r0, r1, r2, r3);
                b[2*j2][0] = r0;  b[2*j2][1] = r1;
                b[2*j2+1][0] = r2; b[2*j2+1][1] = r3;
            }
            #pragma unroll
            for (int i = 0; i < 4; i++)
                #pragma unroll
                for (int j = 0; j < 4; j++)
                    mma16816(acc[i][j], a[i][0], a[i][1], a[i][2], a[i][3], b[j][0], b[j][1]);
        }
    }

    // epilogue: add bias, store float2 pairs
    const int colBase = blockN + wn*32 + 2*(lane & 3);
    float2 bj[4];
    #pragma unroll
    for (int j = 0; j < 4; j++) bj[j] = *(const float2*)(bias + colBase + j*8);

    #pragma unroll
    for (int i = 0; i < 4; i++){
        int row0 = blockM + wm*64 + i*16 + (lane >> 2);
        #pragma unroll
        for (int j = 0; j < 4; j++){
            float2 v0 = make_float2(acc[i][j][0] + bj[j].x, acc[i][j][1] + bj[j].y);
            float2 v1 = make_float2(acc[i][j][2] + bj[j].x, acc[i][j][3] + bj[j].y);
            *(float2*)(g_ts + (size_t)row0 * Nn + colBase + j*8)       = v0;
            *(float2*)(g_ts + (size_t)(row0+8) * Nn + colBase + j*8)   = v1;
        }
    }
}

// ---------------- 4. max-sum scan: register double-buffered pipeline ----------------
struct ScanState {
    float hid[7];
    float sc;
};

__device__ __forceinline__ void scan_load(float2* buf, const float2* base, int t0){
    #pragma unroll
    for (int u = 0; u < 4; u++){
        const float2* q = base + (size_t)(t0 + u) * (Nn/2);
        #pragma unroll
        for (int j = 0; j < 7; j++) buf[u*7 + j] = q[j];
    }
}

__device__ __forceinline__ void scan_compute(ScanState& st, const float2* buf,
                                             const float* eps, bool end5, int dl, int t0){
    #pragma unroll
    for (int u = 0; u < 4; u++){
        float f[14];
        #pragma unroll
        for (int j = 0; j < 7; j++){ f[2*j] = buf[u*7 + j].x; f[2*j+1] = buf[u*7 + j].y; }
        float ae[7];
        ae[0] = st.hid[0];
        #pragma unroll
        for (int m = 1; m < 7; m++) ae[m] = fmaxf(st.hid[m], st.hid[m-1] + eps[m-1]);
        float nh[7];
        nh[0] = fmaxf(0.0f, ae[0] + f[0]);
        #pragma unroll
        for (int m = 1; m < 7; m++)
            nh[m] = fmaxf(ae[m-1] + f[7 + m - 1], ae[m] + f[m]);
        #pragma unroll
        for (int m = 0; m < 7; m++) st.hid[m] = nh[m];
        float endv = end5 ? st.hid[5] : st.hid[6];
        if (t0 + u < dl) st.sc = fmaxf(st.sc, endv);
    }
}

__global__ __launch_bounds__(64) void scan_kernel(const int* __restrict__ doc_lens,
                                                  const float* __restrict__ epsilons)
{
    int idx = blockIdx.x * 64 + threadIdx.x;
    int b = idx >> 9;
    int p = idx & 511;

    float eps[6];
    #pragma unroll
    for (int i = 0; i < 6; i++) eps[i] = epsilons[p*6 + i];
    const bool end5 = (p < 256);
    const int dl = doc_lens[b];

    ScanState st;
    st.hid[0] = 0.0f;
    #pragma unroll
    for (int m = 1; m < 7; m++) st.hid[m] = NEGV;
    st.sc = NEGV;

    const float2* base = (const float2*)(g_ts + (size_t)b * Tt * Nn + (size_t)p * 14);

    float2 buf0[28], buf1[28];
    scan_load(buf0, base, 0);

    #pragma unroll 1
    for (int c = 0; c < 32; c += 2){
        scan_load(buf1, base, (c + 1) * 4);
        scan_compute(st, buf0, eps, end5, dl, c * 4);
        if (c + 2 < 32) scan_load(buf0, base, (c + 2) * 4);
        scan_compute(st, buf1, eps, end5, dl, (c + 1) * 4);
    }
    g_scores[idx] = st.sc;
}

// ---------------- 5. batchnorm + binarize + final linear ----------------
__global__ __launch_bounds__(512) void final_kernel(const float* __restrict__ bn_w,
                                                    const float* __restrict__ bn_b,
                                                    const float* __restrict__ fw,
                                                    const float* __restrict__ fb,
                                                    float* __restrict__ out)
{
    __shared__ unsigned char sbin[Bb][Pp];
    int p = threadIdx.x;

    float x[Bb];
    float s = 0.0f;
    #pragma unroll
    for (int b = 0; b < Bb; b++){ x[b] = g_scores[b*Pp + p]; s += x[b]; }
    float mean = s * (1.0f / Bb);
    float v = 0.0f;
    #pragma unroll
    for (int b = 0; b < Bb; b++){ float d = x[b] - mean; v += d * d; }
    v *= (1.0f / Bb);
    float inv = rsqrtf(v + 1e-5f);
    float w = bn_w[p], bb = bn_b[p];
    #pragma unroll
    for (int b = 0; b < Bb; b++){
        float y = (x[b] - mean) * inv * w + bb;
        sbin[b][p] = (y > 0.0f) ? 1 : 0;
    }
    __syncthreads();

    int warp = p >> 5, lane = p & 31;
    #pragma unroll
    for (int q = 0; q < 4; q++){
        int o = warp * 4 + q;
        int b = o >> 1, c = o & 1;
        float acc = 0.0f;
        for (int pp = lane; pp < Pp; pp += 32)
            if (sbin[b][pp]) acc += fw[c*Pp + pp];
        #pragma unroll
        for (int off = 16; off > 0; off >>= 1)
            acc += __shfl_xor_sync(0xffffffffu, acc, off);
        if (lane == 0) out[b*NCc + c] = acc + fb[c];
    }
}

// ---------------- host launch ----------------
extern "C" void kernel_launch(void* const* d_in, const int* in_sizes, int n_in,
                              void* d_out, int out_size)
{
    const int*   tokens    = (const int*)  d_in[0];
    const int*   doc_lens  = (const int*)  d_in[1];
    const float* emb_table = (const float*)d_in[2];
    const float* diags     = (const float*)d_in[3];
    const float* bias      = (const float*)d_in[4];
    const float* epsilons  = (const float*)d_in[5];
    const float* bn_weight = (const float*)d_in[6];
    const float* bn_bias   = (const float*)d_in[7];
    const float* final_w   = (const float*)d_in[8];
    const float* final_b   = (const float*)d_in[9];
    float* out = (float*)d_out;

    convA_kernel<<<Mm, 128>>>(tokens, emb_table);
    convB_kernel<<<Nn, 128>>>(diags);

    cudaFuncSetAttribute(gemm_kernel, cudaFuncAttributeMaxDynamicSharedMemorySize, SMEM_GEMM);
    dim3 grid(Nn / 128, Mm / 128);   // (56, 32)
    gemm_kernel<<<grid, 256, SMEM_GEMM>>>(bias);

    scan_kernel<<<(Bb*Pp) / 64, 64>>>(doc_lens, epsilons);
    final_kernel<<<1, 512>>>(bn_weight, bn_bias, final_w, final_b, out);
}

// round 5
// speedup vs baseline: 1.2239x; 1.2239x over previous
#include <cuda_runtime.h>
#include <cuda_bf16.h>
#include <cstdint>

// ---------------- problem constants ----------------
#define Bb    32
#define Tt    128
#define Pp    512
#define MAXL  7
#define Dd    300
#define KSEG  304            // per-segment K (>=300, mult of 16)
#define KP    (4*KSEG)       // 1216 = 38*32
#define Nn    7168           // P*ND*MAXL
#define Mm    4096           // B*T
#define NCc   2
#define NEGV  (-1e30f)

// gemm tiling: CTA 128(M) x 256(N), 8 warps (2M x 4N), warp tile 64x64
#define TILE_M 128
#define TILE_N 256
#define BK    32
#define NKT   (KP/BK)        // 38
#define NSTG  4
#define ROWB  80             // smem row stride bytes (64 data + 16 pad)
#define STAGE_A   (TILE_M*ROWB)          // 10240
#define STAGE_B   (TILE_N*ROWB)          // 20480
#define STAGE_SZ  (STAGE_A+STAGE_B)      // 30720
#define SMEM_GEMM (NSTG*STAGE_SZ)        // 122880

// ---------------- scratch ----------------
__device__ __nv_bfloat16 g_Aq[(size_t)Mm * KP];   // [h,h,m,m]
__device__ __nv_bfloat16 g_Bq[(size_t)Nn * KP];   // [h,m,h,m]
__device__ float g_ts[(size_t)Mm * Nn];           // 117 MB
__device__ float g_scores[Bb * Pp];

// ---------------- PTX helpers ----------------
__device__ __forceinline__ void cpasync16(uint32_t s, const void* g){
    asm volatile("cp.async.cg.shared.global [%0], [%1], 16;" :: "r"(s), "l"(g));
}
__device__ __forceinline__ void cp_commit(){
    asm volatile("cp.async.commit_group;" ::: "memory");
}
template<int N> __device__ __forceinline__ void cp_wait(){
    asm volatile("cp.async.wait_group %0;" :: "n"(N) : "memory");
}
__device__ __forceinline__ void ldsm4(uint32_t a, uint32_t& r0, uint32_t& r1, uint32_t& r2, uint32_t& r3){
    asm volatile("ldmatrix.sync.aligned.m8n8.x4.shared.b16 {%0,%1,%2,%3}, [%4];"
                 : "=r"(r0), "=r"(r1), "=r"(r2), "=r"(r3) : "r"(a));
}
__device__ __forceinline__ void mma16816(float* c, uint32_t a0, uint32_t a1, uint32_t a2, uint32_t a3,
                                         uint32_t b0, uint32_t b1){
    asm volatile("mma.sync.aligned.m16n8k16.row.col.f32.bf16.bf16.f32 "
                 "{%0,%1,%2,%3}, {%4,%5,%6,%7}, {%8,%9}, {%0,%1,%2,%3};"
                 : "+f"(c[0]), "+f"(c[1]), "+f"(c[2]), "+f"(c[3])
                 : "r"(a0), "r"(a1), "r"(a2), "r"(a3), "r"(b0), "r"(b1));
}

// ---------------- 1/2. bf16 split-precision conversion ----------------
__global__ void convA_kernel(const int* __restrict__ tokens, const float* __restrict__ emb){
    int mrow = blockIdx.x;
    int tok = tokens[mrow];
    __nv_bfloat16* row = g_Aq + (size_t)mrow * KP;
    const float* src = emb + (size_t)tok * Dd;
    for (int k = threadIdx.x; k < KSEG; k += blockDim.x){
        float x = (k < Dd) ? src[k] : 0.0f;
        __nv_bfloat16 h = __float2bfloat16(x);
        __nv_bfloat16 m = __float2bfloat16(x - __bfloat162float(h));
        row[0*KSEG + k] = h;  row[1*KSEG + k] = h;
        row[2*KSEG + k] = m;  row[3*KSEG + k] = m;
    }
}
__global__ void convB_kernel(const float* __restrict__ diags){
    int n = blockIdx.x;
    __nv_bfloat16* row = g_Bq + (size_t)n * KP;
    const float* src = diags + (size_t)n * Dd;
    for (int k = threadIdx.x; k < KSEG; k += blockDim.x){
        float x = (k < Dd) ? src[k] : 0.0f;
        __nv_bfloat16 h = __float2bfloat16(x);
        __nv_bfloat16 m = __float2bfloat16(x - __bfloat162float(h));
        row[0*KSEG + k] = h;  row[1*KSEG + k] = m;
        row[2*KSEG + k] = h;  row[3*KSEG + k] = m;
    }
}

// ---------------- 3. bf16 mma.sync GEMM: ts[m][n] = sum_k A'[m][k]*B'[n][k] + bias[n] ----------------
__global__ __launch_bounds__(256, 1) void gemm_kernel(const float* __restrict__ bias)
{
    extern __shared__ char smem[];
    const uint32_t sb = (uint32_t)__cvta_generic_to_shared(smem);
    const int tid = threadIdx.x;
    const int lane = tid & 31, wid = tid >> 5;
    const int wm = wid & 1, wn = wid >> 1;
    const int blockM = blockIdx.y * TILE_M;
    const int blockN = blockIdx.x * TILE_N;

    const __nv_bfloat16* gA = g_Aq + (size_t)blockM * KP;
    const __nv_bfloat16* gB = g_Bq + (size_t)blockN * KP;

    // cp.async: 3 tasks of 32B per thread.
    // task id: [0,256) -> A (row=id>>1, half=id&1); [256,768) -> B
    uint32_t t_soff[3];
    const __nv_bfloat16* t_gptr[3];
    #pragma unroll
    for (int q = 0; q < 3; q++){
        int id = tid + q*256;
        int isB = (id >= 256);
        int lid2 = isB ? (id - 256) : id;
        int row = lid2 >> 1, half = lid2 & 1;
        t_soff[q] = (isB ? STAGE_A : 0) + row*ROWB + half*32;
        t_gptr[q] = (isB ? gB : gA) + (size_t)row * KP + half*16;
    }

    // ldmatrix source addresses
    const uint32_t aBase = sb + (wm*64 + (lane & 15)) * ROWB + (lane >> 4) * 16;
    const uint32_t bBase = sb + STAGE_A + (wn*64 + ((lane >> 4) << 3) + (lane & 7)) * ROWB
                              + (((lane >> 3) & 1) * 16);

    float acc[4][8][4];
    #pragma unroll
    for (int i = 0; i < 4; i++)
        #pragma unroll
        for (int j = 0; j < 8; j++)
            #pragma unroll
            for (int r = 0; r < 4; r++) acc[i][j][r] = 0.0f;

    // prologue
    #pragma unroll
    for (int s = 0; s < NSTG-1; s++){
        #pragma unroll
        for (int q = 0; q < 3; q++){
            uint32_t st = sb + s*STAGE_SZ + t_soff[q];
            const __nv_bfloat16* gp = t_gptr[q] + s*BK;
            cpasync16(st,      gp);
            cpasync16(st + 16, gp + 8);
        }
        cp_commit();
    }

    for (int kt = 0; kt < NKT; kt++){
        cp_wait<NSTG-2>();
        __syncthreads();

        int nkt = kt + NSTG - 1;
        if (nkt < NKT){
            uint32_t stb = sb + (nkt % NSTG)*STAGE_SZ;
            #pragma unroll
            for (int q = 0; q < 3; q++){
                uint32_t st = stb + t_soff[q];
                const __nv_bfloat16* gp = t_gptr[q] + nkt*BK;
                cpasync16(st,      gp);
                cpasync16(st + 16, gp + 8);
            }
        }
        cp_commit();

        const uint32_t stage = (kt % NSTG) * STAGE_SZ;
        #pragma unroll
        for (int s = 0; s < 2; s++){
            uint32_t a[4][4], b[8][2];
            #pragma unroll
            for (int i = 0; i < 4; i++)
                ldsm4(aBase + stage + i*16*ROWB + s*32, a[i][0], a[i][1], a[i][2], a[i][3]);
            #pragma unroll
            for (int j2 = 0; j2 < 4; j2++){
                uint32_t r0, r1, r2, r3;
                ldsm4(bBase + stage + j2*16*ROWB + s*32, r0, r1, r2, r3);
                b[2*j2][0] = r0;   b[2*j2][1] = r1;
                b[2*j2+1][0] = r2; b[2*j2+1][1] = r3;
            }
            #pragma unroll
            for (int i = 0; i < 4; i++)
                #pragma unroll
                for (int j = 0; j < 8; j++)
                    mma16816(acc[i][j], a[i][0], a[i][1], a[i][2], a[i][3], b[j][0], b[j][1]);
        }
    }

    // epilogue: add bias, store float2 pairs
    const int colBase = blockN + wn*64 + 2*(lane & 3);
    #pragma unroll
    for (int i = 0; i < 4; i++){
        int row0 = blockM + wm*64 + i*16 + (lane >> 2);
        float* r0p = g_ts + (size_t)row0 * Nn + colBase;
        float* r1p = r0p + (size_t)8 * Nn;
        #pragma unroll
        for (int j = 0; j < 8; j++){
            float2 bj = *(const float2*)(bias + colBase + j*8);
            float2 v0 = make_float2(acc[i][j][0] + bj.x, acc[i][j][1] + bj.y);
            float2 v1 = make_float2(acc[i][j][2] + bj.x, acc[i][j][3] + bj.y);
            *(float2*)(r0p + j*8) = v0;
            *(float2*)(r1p + j*8) = v1;
        }
    }
}

// ---------------- 4. max-sum scan: register double-buffered pipeline ----------------
struct ScanState {
    float hid[7];
    float sc;
};

__device__ __forceinline__ void scan_load(float2* buf, const float2* base, int t0){
    #pragma unroll
    for (int u = 0; u < 4; u++){
        const float2* q = base + (size_t)(t0 + u) * (Nn/2);
        #pragma unroll
        for (int j = 0; j < 7; j++) buf[u*7 + j] = q[j];
    }
}

__device__ __forceinline__ void scan_compute(ScanState& st, const float2* buf,
                                             const float* eps, bool end5, int dl, int t0){
    #pragma unroll
    for (int u = 0; u < 4; u++){
        float f[14];
        #pragma unroll
        for (int j = 0; j < 7; j++){ f[2*j] = buf[u*7 + j].x; f[2*j+1] = buf[u*7 + j].y; }
        float ae[7];
        ae[0] = st.hid[0];
        #pragma unroll
        for (int m = 1; m < 7; m++) ae[m] = fmaxf(st.hid[m], st.hid[m-1] + eps[m-1]);
        float nh[7];
        nh[0] = fmaxf(0.0f, ae[0] + f[0]);
        #pragma unroll
        for (int m = 1; m < 7; m++)
            nh[m] = fmaxf(ae[m-1] + f[7 + m - 1], ae[m] + f[m]);
        #pragma unroll
        for (int m = 0; m < 7; m++) st.hid[m] = nh[m];
        float endv = end5 ? st.hid[5] : st.hid[6];
        if (t0 + u < dl) st.sc = fmaxf(st.sc, endv);
    }
}

__global__ __launch_bounds__(64) void scan_kernel(const int* __restrict__ doc_lens,
                                                  const float* __restrict__ epsilons)
{
    int idx = blockIdx.x * 64 + threadIdx.x;
    int b = idx >> 9;
    int p = idx & 511;

    float eps[6];
    #pragma unroll
    for (int i = 0; i < 6; i++) eps[i] = epsilons[p*6 + i];
    const bool end5 = (p < 256);
    const int dl = doc_lens[b];

    ScanState st;
    st.hid[0] = 0.0f;
    #pragma unroll
    for (int m = 1; m < 7; m++) st.hid[m] = NEGV;
    st.sc = NEGV;

    const float2* base = (const float2*)(g_ts + (size_t)b * Tt * Nn + (size_t)p * 14);

    float2 buf0[28], buf1[28];
    scan_load(buf0, base, 0);

    #pragma unroll 1
    for (int c = 0; c < 32; c += 2){
        scan_load(buf1, base, (c + 1) * 4);
        scan_compute(st, buf0, eps, end5, dl, c * 4);
        if (c + 2 < 32) scan_load(buf0, base, (c + 2) * 4);
        scan_compute(st, buf1, eps, end5, dl, (c + 1) * 4);
    }
    g_scores[idx] = st.sc;
}

// ---------------- 5. batchnorm + binarize + final linear ----------------
__global__ __launch_bounds__(512) void final_kernel(const float* __restrict__ bn_w,
                                                    const float* __restrict__ bn_b,
                                                    const float* __restrict__ fw,
                                                    const float* __restrict__ fb,
                                                    float* __restrict__ out)
{
    __shared__ unsigned char sbin[Bb][Pp];
    int p = threadIdx.x;

    float x[Bb];
    float s = 0.0f;
    #pragma unroll
    for (int b = 0; b < Bb; b++){ x[b] = g_scores[b*Pp + p]; s += x[b]; }
    float mean = s * (1.0f / Bb);
    float v = 0.0f;
    #pragma unroll
    for (int b = 0; b < Bb; b++){ float d = x[b] - mean; v += d * d; }
    v *= (1.0f / Bb);
    float inv = rsqrtf(v + 1e-5f);
    float w = bn_w[p], bb = bn_b[p];
    #pragma unroll
    for (int b = 0; b < Bb; b++){
        float y = (x[b] - mean) * inv * w + bb;
        sbin[b][p] = (y > 0.0f) ? 1 : 0;
    }
    __syncthreads();

    int warp = p >> 5, lane = p & 31;
    #pragma unroll
    for (int q = 0; q < 4; q++){
        int o = warp * 4 + q;
        int b = o >> 1, c = o & 1;
        float acc = 0.0f;
        for (int pp = lane; pp < Pp; pp += 32)
            if (sbin[b][pp]) acc += fw[c*Pp + pp];
        #pragma unroll
        for (int off = 16; off > 0; off >>= 1)
            acc += __shfl_xor_sync(0xffffffffu, acc, off);
        if (lane == 0) out[b*NCc + c] = acc + fb[c];
    }
}

// ---------------- host launch ----------------
extern "C" void kernel_launch(void* const* d_in, const int* in_sizes, int n_in,
                              void* d_out, int out_size)
{
    const int*   tokens    = (const int*)  d_in[0];
    const int*   doc_lens  = (const int*)  d_in[1];
    const float* emb_table = (const float*)d_in[2];
    const float* diags     = (const float*)d_in[3];
    const float* bias      = (const float*)d_in[4];
    const float* epsilons  = (const float*)d_in[5];
    const float* bn_weight = (const float*)d_in[6];
    const float* bn_bias   = (const float*)d_in[7];
    const float* final_w   = (const float*)d_in[8];
    const float* final_b   = (const float*)d_in[9];
    float* out = (float*)d_out;

    convA_kernel<<<Mm, 128>>>(tokens, emb_table);
    convB_kernel<<<Nn, 128>>>(diags);

    cudaFuncSetAttribute(gemm_kernel, cudaFuncAttributeMaxDynamicSharedMemorySize, SMEM_GEMM);
    dim3 grid(Nn / TILE_N, Mm / TILE_M);   // (28, 32)
    gemm_kernel<<<grid, 256, SMEM_GEMM>>>(bias);

    scan_kernel<<<(Bb*Pp) / 64, 64>>>(doc_lens, epsilons);
    final_kernel<<<1, 512>>>(bn_weight, bn_bias, final_w, final_b, out);
}

// round 6
// speedup vs baseline: 1.4253x; 1.1645x over previous
#include <cuda_runtime.h>
#include <cuda_bf16.h>
#include <cstdint>

// ---------------- problem constants ----------------
#define Bb    32
#define Tt    128
#define Pp    512
#define MAXL  7
#define Dd    300
#define KSEG  304            // per-segment K (>=300, mult of 16)
#define KP    (4*KSEG)       // 1216 = 38*32
#define Nn    7168           // P*ND*MAXL
#define Mm    4096           // B*T (max)
#define NCc   2
#define NEGV  (-1e30f)

// gemm tiling: CTA 128(M) x 256(N), 8 warps (2M x 4N), warp tile 64x64
#define TILE_M 128
#define TILE_N 256
#define BK    32
#define NKT   (KP/BK)        // 38
#define NSTG  4
#define ROWB  80             // smem row stride bytes (64 data + 16 pad)
#define STAGE_A   (TILE_M*ROWB)          // 10240
#define STAGE_B   (TILE_N*ROWB)          // 20480
#define STAGE_SZ  (STAGE_A+STAGE_B)      // 30720
#define SMEM_GEMM (NSTG*STAGE_SZ)        // 122880

// ---------------- scratch ----------------
__device__ __nv_bfloat16 g_Aq[(size_t)Mm * KP];   // [h,h,m,m], M-compacted
__device__ __nv_bfloat16 g_Bq[(size_t)Nn * KP];   // [h,m,h,m]
__device__ float g_ts[(size_t)Mm * Nn];           // 117 MB, M-compacted
__device__ float g_scores[Bb * Pp];
__device__ int   g_off[Bb + 1];                   // row offsets per doc
__device__ int   g_padTo;                         // total rows padded to TILE_M

// ---------------- PTX helpers ----------------
__device__ __forceinline__ void cpasync16(uint32_t s, const void* g){
    asm volatile("cp.async.cg.shared.global [%0], [%1], 16;" :: "r"(s), "l"(g));
}
__device__ __forceinline__ void cp_commit(){
    asm volatile("cp.async.commit_group;" ::: "memory");
}
template<int N> __device__ __forceinline__ void cp_wait(){
    asm volatile("cp.async.wait_group %0;" :: "n"(N) : "memory");
}
__device__ __forceinline__ void ldsm4(uint32_t a, uint32_t& r0, uint32_t& r1, uint32_t& r2, uint32_t& r3){
    asm volatile("ldmatrix.sync.aligned.m8n8.x4.shared.b16 {%0,%1,%2,%3}, [%4];"
                 : "=r"(r0), "=r"(r1), "=r"(r2), "=r"(r3) : "r"(a));
}
__device__ __forceinline__ void mma16816(float* c, uint32_t a0, uint32_t a1, uint32_t a2, uint32_t a3,
                                         uint32_t b0, uint32_t b1){
    asm volatile("mma.sync.aligned.m16n8k16.row.col.f32.bf16.bf16.f32 "
                 "{%0,%1,%2,%3}, {%4,%5,%6,%7}, {%8,%9}, {%0,%1,%2,%3};"
                 : "+f"(c[0]), "+f"(c[1]), "+f"(c[2]), "+f"(c[3])
                 : "r"(a0), "r"(a1), "r"(a2), "r"(a3), "r"(b0), "r"(b1));
}

// ---------------- 0. doc-length prefix offsets ----------------
__global__ void offsets_kernel(const int* __restrict__ doc_lens){
    if (threadIdx.x == 0){
        int acc = 0;
        for (int b = 0; b < Bb; b++){ g_off[b] = acc; acc += doc_lens[b]; }
        g_off[Bb] = acc;
        g_padTo = (acc + TILE_M - 1) & ~(TILE_M - 1);
    }
}

// ---------------- 1/2. bf16 split-precision conversion (A compacted) ----------------
__global__ void convA_kernel(const int* __restrict__ tokens, const float* __restrict__ emb,
                             const int* __restrict__ doc_lens){
    int b = blockIdx.x >> 7, t = blockIdx.x & 127;
    if (t >= doc_lens[b]) return;
    int mrow = g_off[b] + t;
    int tok = tokens[blockIdx.x];
    __nv_bfloat16* row = g_Aq + (size_t)mrow * KP;
    const float* src = emb + (size_t)tok * Dd;
    for (int k = threadIdx.x; k < KSEG; k += blockDim.x){
        float x = (k < Dd) ? src[k] : 0.0f;
        __nv_bfloat16 h = __float2bfloat16(x);
        __nv_bfloat16 m = __float2bfloat16(x - __bfloat162float(h));
        row[0*KSEG + k] = h;  row[1*KSEG + k] = h;
        row[2*KSEG + k] = m;  row[3*KSEG + k] = m;
    }
}
__global__ void convB_kernel(const float* __restrict__ diags){
    int n = blockIdx.x;
    __nv_bfloat16* row = g_Bq + (size_t)n * KP;
    const float* src = diags + (size_t)n * Dd;
    for (int k = threadIdx.x; k < KSEG; k += blockDim.x){
        float x = (k < Dd) ? src[k] : 0.0f;
        __nv_bfloat16 h = __float2bfloat16(x);
        __nv_bfloat16 m = __float2bfloat16(x - __bfloat162float(h));
        row[0*KSEG + k] = h;  row[1*KSEG + k] = m;
        row[2*KSEG + k] = h;  row[3*KSEG + k] = m;
    }
}

// ---------------- 3. bf16 mma.sync GEMM (compacted M, early-exit tiles) ----------------
__global__ __launch_bounds__(256, 1) void gemm_kernel(const float* __restrict__ bias)
{
    const int blockM = blockIdx.y * TILE_M;
    if (blockM >= g_padTo) return;     // uniform across CTA

    extern __shared__ char smem[];
    const uint32_t sb = (uint32_t)__cvta_generic_to_shared(smem);
    const int tid = threadIdx.x;
    const int lane = tid & 31, wid = tid >> 5;
    const int wm = wid & 1, wn = wid >> 1;
    const int blockN = blockIdx.x * TILE_N;

    const __nv_bfloat16* gA = g_Aq + (size_t)blockM * KP;
    const __nv_bfloat16* gB = g_Bq + (size_t)blockN * KP;

    // cp.async: 3 tasks of 32B per thread.
    uint32_t t_soff[3];
    const __nv_bfloat16* t_gptr[3];
    #pragma unroll
    for (int q = 0; q < 3; q++){
        int id = tid + q*256;
        int isB = (id >= 256);
        int lid2 = isB ? (id - 256) : id;
        int row = lid2 >> 1, half = lid2 & 1;
        t_soff[q] = (isB ? STAGE_A : 0) + row*ROWB + half*32;
        t_gptr[q] = (isB ? gB : gA) + (size_t)row * KP + half*16;
    }

    const uint32_t aBase = sb + (wm*64 + (lane & 15)) * ROWB + (lane >> 4) * 16;
    const uint32_t bBase = sb + STAGE_A + (wn*64 + ((lane >> 4) << 3) + (lane & 7)) * ROWB
                              + (((lane >> 3) & 1) * 16);

    float acc[4][8][4];
    #pragma unroll
    for (int i = 0; i < 4; i++)
        #pragma unroll
        for (int j = 0; j < 8; j++)
            #pragma unroll
            for (int r = 0; r < 4; r++) acc[i][j][r] = 0.0f;

    #pragma unroll
    for (int s = 0; s < NSTG-1; s++){
        #pragma unroll
        for (int q = 0; q < 3; q++){
            uint32_t st = sb + s*STAGE_SZ + t_soff[q];
            const __nv_bfloat16* gp = t_gptr[q] + s*BK;
            cpasync16(st,      gp);
            cpasync16(st + 16, gp + 8);
        }
        cp_commit();
    }

    for (int kt = 0; kt < NKT; kt++){
        cp_wait<NSTG-2>();
        __syncthreads();

        int nkt = kt + NSTG - 1;
        if (nkt < NKT){
            uint32_t stb = sb + (nkt % NSTG)*STAGE_SZ;
            #pragma unroll
            for (int q = 0; q < 3; q++){
                uint32_t st = stb + t_soff[q];
                const __nv_bfloat16* gp = t_gptr[q] + nkt*BK;
                cpasync16(st,      gp);
                cpasync16(st + 16, gp + 8);
            }
        }
        cp_commit();

        const uint32_t stage = (kt % NSTG) * STAGE_SZ;
        #pragma unroll
        for (int s = 0; s < 2; s++){
            uint32_t a[4][4], b[8][2];
            #pragma unroll
            for (int i = 0; i < 4; i++)
                ldsm4(aBase + stage + i*16*ROWB + s*32, a[i][0], a[i][1], a[i][2], a[i][3]);
            #pragma unroll
            for (int j2 = 0; j2 < 4; j2++){
                uint32_t r0, r1, r2, r3;
                ldsm4(bBase + stage + j2*16*ROWB + s*32, r0, r1, r2, r3);
                b[2*j2][0] = r0;   b[2*j2][1] = r1;
                b[2*j2+1][0] = r2; b[2*j2+1][1] = r3;
            }
            #pragma unroll
            for (int i = 0; i < 4; i++)
                #pragma unroll
                for (int j = 0; j < 8; j++)
                    mma16816(acc[i][j], a[i][0], a[i][1], a[i][2], a[i][3], b[j][0], b[j][1]);
        }
    }

    const int colBase = blockN + wn*64 + 2*(lane & 3);
    #pragma unroll
    for (int i = 0; i < 4; i++){
        int row0 = blockM + wm*64 + i*16 + (lane >> 2);
        float* r0p = g_ts + (size_t)row0 * Nn + colBase;
        float* r1p = r0p + (size_t)8 * Nn;
        #pragma unroll
        for (int j = 0; j < 8; j++){
            float2 bj = *(const float2*)(bias + colBase + j*8);
            float2 v0 = make_float2(acc[i][j][0] + bj.x, acc[i][j][1] + bj.y);
            float2 v1 = make_float2(acc[i][j][2] + bj.x, acc[i][j][3] + bj.y);
            *(float2*)(r0p + j*8) = v0;
            *(float2*)(r1p + j*8) = v1;
        }
    }
}

// ---------------- 4. max-sum scan: compacted rows, runtime trip count ----------------
struct ScanState {
    float hid[7];
    float sc;
};

__device__ __forceinline__ void scan_load(float2* buf, const float2* base, int chunk){
    #pragma unroll
    for (int u = 0; u < 4; u++){
        const float2* q = base + (size_t)(chunk*4 + u) * (Nn/2);
        #pragma unroll
        for (int j = 0; j < 7; j++) buf[u*7 + j] = q[j];
    }
}

__device__ __forceinline__ void scan_step(ScanState& st, const float* f,
                                          const float* eps, bool end5){
    float ae[7];
    ae[0] = st.hid[0];
    #pragma unroll
    for (int m = 1; m < 7; m++) ae[m] = fmaxf(st.hid[m], st.hid[m-1] + eps[m-1]);
    float nh[7];
    nh[0] = fmaxf(0.0f, ae[0] + f[0]);
    #pragma unroll
    for (int m = 1; m < 7; m++)
        nh[m] = fmaxf(ae[m-1] + f[7 + m - 1], ae[m] + f[m]);
    #pragma unroll
    for (int m = 0; m < 7; m++) st.hid[m] = nh[m];
    st.sc = fmaxf(st.sc, end5 ? st.hid[5] : st.hid[6]);
}

__device__ __forceinline__ void scan_compute(ScanState& st, const float2* buf,
                                             const float* eps, bool end5){
    #pragma unroll
    for (int u = 0; u < 4; u++){
        float f[14];
        #pragma unroll
        for (int j = 0; j < 7; j++){ f[2*j] = buf[u*7 + j].x; f[2*j+1] = buf[u*7 + j].y; }
        scan_step(st, f, eps, end5);
    }
}

__global__ __launch_bounds__(64) void scan_kernel(const int* __restrict__ doc_lens,
                                                  const float* __restrict__ epsilons)
{
    int idx = blockIdx.x * 64 + threadIdx.x;
    int b = idx >> 9;
    int p = idx & 511;

    float eps[6];
    #pragma unroll
    for (int i = 0; i < 6; i++) eps[i] = epsilons[p*6 + i];
    const bool end5 = (p < 256);
    const int dl = doc_lens[b];
    const int n4 = dl >> 2, rem = dl & 3;

    ScanState st;
    st.hid[0] = 0.0f;
    #pragma unroll
    for (int m = 1; m < 7; m++) st.hid[m] = NEGV;
    st.sc = NEGV;

    const float2* base = (const float2*)(g_ts + (size_t)g_off[b] * Nn + (size_t)p * 14);

    float2 buf0[28], buf1[28];
    scan_load(buf0, base, 0);

    int c = 0;
    #pragma unroll 1
    while (c + 2 <= n4){
        scan_load(buf1, base, c + 1);
        scan_compute(st, buf0, eps, end5);
        if (c + 2 < n4) scan_load(buf0, base, c + 2);
        scan_compute(st, buf1, eps, end5);
        c += 2;
    }
    if (c < n4){                          // odd n4: last chunk already in buf0
        scan_compute(st, buf0, eps, end5);
    }
    #pragma unroll 1
    for (int u = 0; u < rem; u++){        // tail steps
        const float2* q = base + (size_t)(n4*4 + u) * (Nn/2);
        float f[14];
        #pragma unroll
        for (int j = 0; j < 7; j++){ float2 v = q[j]; f[2*j] = v.x; f[2*j+1] = v.y; }
        scan_step(st, f, eps, end5);
    }
    g_scores[idx] = st.sc;
}

// ---------------- 5. batchnorm + binarize + final linear ----------------
__global__ __launch_bounds__(512) void final_kernel(const float* __restrict__ bn_w,
                                                    const float* __restrict__ bn_b,
                                                    const float* __restrict__ fw,
                                                    const float* __restrict__ fb,
                                                    float* __restrict__ out)
{
    __shared__ unsigned char sbin[Bb][Pp];
    int p = threadIdx.x;

    float x[Bb];
    float s = 0.0f;
    #pragma unroll
    for (int b = 0; b < Bb; b++){ x[b] = g_scores[b*Pp + p]; s += x[b]; }
    float mean = s * (1.0f / Bb);
    float v = 0.0f;
    #pragma unroll
    for (int b = 0; b < Bb; b++){ float d = x[b] - mean; v += d * d; }
    v *= (1.0f / Bb);
    float inv = rsqrtf(v + 1e-5f);
    float w = bn_w[p], bb = bn_b[p];
    #pragma unroll
    for (int b = 0; b < Bb; b++){
        float y = (x[b] - mean) * inv * w + bb;
        sbin[b][p] = (y > 0.0f) ? 1 : 0;
    }
    __syncthreads();

    int warp = p >> 5, lane = p & 31;
    #pragma unroll
    for (int q = 0; q < 4; q++){
        int o = warp * 4 + q;
        int b = o >> 1, c = o & 1;
        float acc = 0.0f;
        for (int pp = lane; pp < Pp; pp += 32)
            if (sbin[b][pp]) acc += fw[c*Pp + pp];
        #pragma unroll
        for (int off = 16; off > 0; off >>= 1)
            acc += __shfl_xor_sync(0xffffffffu, acc, off);
        if (lane == 0) out[b*NCc + c] = acc + fb[c];
    }
}

// ---------------- host launch ----------------
extern "C" void kernel_launch(void* const* d_in, const int* in_sizes, int n_in,
                              void* d_out, int out_size)
{
    const int*   tokens    = (const int*)  d_in[0];
    const int*   doc_lens  = (const int*)  d_in[1];
    const float* emb_table = (const float*)d_in[2];
    const float* diags     = (const float*)d_in[3];
    const float* bias      = (const float*)d_in[4];
    const float* epsilons  = (const float*)d_in[5];
    const float* bn_weight = (const float*)d_in[6];
    const float* bn_bias   = (const float*)d_in[7];
    const float* final_w   = (const float*)d_in[8];
    const float* final_b   = (const float*)d_in[9];
    float* out = (float*)d_out;

    offsets_kernel<<<1, 32>>>(doc_lens);
    convA_kernel<<<Mm, 128>>>(tokens, emb_table, doc_lens);
    convB_kernel<<<Nn, 128>>>(diags);

    cudaFuncSetAttribute(gemm_kernel, cudaFuncAttributeMaxDynamicSharedMemorySize, SMEM_GEMM);
    dim3 grid(Nn / TILE_N, Mm / TILE_M);   // (28, 32); M-tiles beyond padTo exit
    gemm_kernel<<<grid, 256, SMEM_GEMM>>>(bias);

    scan_kernel<<<(Bb*Pp) / 64, 64>>>(doc_lens, epsilons);
    final_kernel<<<1, 512>>>(bn_weight, bn_bias, final_w, final_b, out);
}

// round 7
// speedup vs baseline: 1.5360x; 1.0777x over previous
#include <cuda_runtime.h>
#include <cuda_bf16.h>
#include <cstdint>

// ---------------- problem constants ----------------
#define Bb    32
#define Tt    128
#define Pp    512
#define MAXL  7
#define Dd    300
#define KSEG  304            // per-segment K (>=300, mult of 16)
#define KP    (4*KSEG)       // 1216 = 38*32
#define Nn    7168           // P*ND*MAXL
#define Mm    4096           // B*T (max)
#define NCc   2
#define NEGV  (-1e30f)

// gemm tiling: CTA 128(M) x 256(N), 16 warps (2M x 8N), warp tile 64x32
#define TILE_M 128
#define TILE_N 256
#define BK    32
#define NKT   (KP/BK)        // 38
#define NSTG  4
#define ROWB  80             // smem row stride bytes (64 data + 16 pad)
#define STAGE_A   (TILE_M*ROWB)          // 10240
#define STAGE_B   (TILE_N*ROWB)          // 20480
#define STAGE_SZ  (STAGE_A+STAGE_B)      // 30720
#define SMEM_GEMM (NSTG*STAGE_SZ)        // 122880

// ---------------- scratch ----------------
__device__ __nv_bfloat16 g_Aq[(size_t)Mm * KP];   // [h,h,m,m], M-compacted
__device__ __nv_bfloat16 g_Bq[(size_t)Nn * KP];   // [h,m,h,m]
__device__ float g_ts[(size_t)Mm * Nn];           // M-compacted
__device__ float g_scores[Bb * Pp];
__device__ int   g_off[Bb + 1];
__device__ int   g_padTo;

// ---------------- PTX helpers ----------------
__device__ __forceinline__ void cpasync16(uint32_t s, const void* g){
    asm volatile("cp.async.cg.shared.global [%0], [%1], 16;" :: "r"(s), "l"(g));
}
__device__ __forceinline__ void cp_commit(){
    asm volatile("cp.async.commit_group;" ::: "memory");
}
template<int N> __device__ __forceinline__ void cp_wait(){
    asm volatile("cp.async.wait_group %0;" :: "n"(N) : "memory");
}
__device__ __forceinline__ void ldsm4(uint32_t a, uint32_t& r0, uint32_t& r1, uint32_t& r2, uint32_t& r3){
    asm volatile("ldmatrix.sync.aligned.m8n8.x4.shared.b16 {%0,%1,%2,%3}, [%4];"
                 : "=r"(r0), "=r"(r1), "=r"(r2), "=r"(r3) : "r"(a));
}
__device__ __forceinline__ void mma16816(float* c, uint32_t a0, uint32_t a1, uint32_t a2, uint32_t a3,
                                         uint32_t b0, uint32_t b1){
    asm volatile("mma.sync.aligned.m16n8k16.row.col.f32.bf16.bf16.f32 "
                 "{%0,%1,%2,%3}, {%4,%5,%6,%7}, {%8,%9}, {%0,%1,%2,%3};"
                 : "+f"(c[0]), "+f"(c[1]), "+f"(c[2]), "+f"(c[3])
                 : "r"(a0), "r"(a1), "r"(a2), "r"(a3), "r"(b0), "r"(b1));
}

// ---------------- 0. doc-length prefix offsets ----------------
__global__ void offsets_kernel(const int* __restrict__ doc_lens){
    if (threadIdx.x == 0){
        int acc = 0;
        for (int b = 0; b < Bb; b++){ g_off[b] = acc; acc += doc_lens[b]; }
        g_off[Bb] = acc;
        g_padTo = (acc + TILE_M - 1) & ~(TILE_M - 1);
    }
}

// ---------------- 1/2. bf16 split-precision conversion ----------------
__global__ void convA_kernel(const int* __restrict__ tokens, const float* __restrict__ emb,
                             const int* __restrict__ doc_lens){
    int b = blockIdx.x >> 7, t = blockIdx.x & 127;
    if (t >= doc_lens[b]) return;
    int mrow = g_off[b] + t;
    int tok = tokens[blockIdx.x];
    __nv_bfloat16* row = g_Aq + (size_t)mrow * KP;
    const float* src = emb + (size_t)tok * Dd;
    for (int k = threadIdx.x; k < KSEG; k += blockDim.x){
        float x = (k < Dd) ? src[k] : 0.0f;
        __nv_bfloat16 h = __float2bfloat16(x);
        __nv_bfloat16 m = __float2bfloat16(x - __bfloat162float(h));
        row[0*KSEG + k] = h;  row[1*KSEG + k] = h;
        row[2*KSEG + k] = m;  row[3*KSEG + k] = m;
    }
}
__global__ void convB_kernel(const float* __restrict__ diags){
    int n = blockIdx.x;
    __nv_bfloat16* row = g_Bq + (size_t)n * KP;
    const float* src = diags + (size_t)n * Dd;
    for (int k = threadIdx.x; k < KSEG; k += blockDim.x){
        float x = (k < Dd) ? src[k] : 0.0f;
        __nv_bfloat16 h = __float2bfloat16(x);
        __nv_bfloat16 m = __float2bfloat16(x - __bfloat162float(h));
        row[0*KSEG + k] = h;  row[1*KSEG + k] = m;
        row[2*KSEG + k] = h;  row[3*KSEG + k] = m;
    }
}

// ---------------- 3. bf16 mma.sync GEMM: 512 threads, 16 warps (2M x 8N) ----------------
__global__ __launch_bounds__(512, 1) void gemm_kernel(const float* __restrict__ bias)
{
    const int blockM = blockIdx.y * TILE_M;
    if (blockM >= g_padTo) return;

    extern __shared__ char smem[];
    const uint32_t sb = (uint32_t)__cvta_generic_to_shared(smem);
    const int tid = threadIdx.x;
    const int lane = tid & 31, wid = tid >> 5;
    const int wm = wid & 1, wn = wid >> 1;       // 2M x 8N
    const int blockN = blockIdx.x * TILE_N;

    const __nv_bfloat16* gA = g_Aq + (size_t)blockM * KP;
    const __nv_bfloat16* gB = g_Bq + (size_t)blockN * KP;

    // cp.async: 3 tasks of 16B per thread. 384 rows x 4 chunks = 1536 tasks.
    uint32_t t_soff[3];
    const __nv_bfloat16* t_gptr[3];
    #pragma unroll
    for (int q = 0; q < 3; q++){
        int id = tid + q*512;
        int row = id >> 2, ch = id & 3;          // row 0..383, chunk 0..3 (16B)
        int isB = (row >= TILE_M);
        int r2  = isB ? (row - TILE_M) : row;
        t_soff[q] = (isB ? STAGE_A : 0) + r2*ROWB + ch*16;
        t_gptr[q] = (isB ? gB : gA) + (size_t)r2 * KP + ch*8;
    }

    // ldmatrix source addresses
    const uint32_t aBase = sb + (wm*64 + (lane & 15)) * ROWB + (lane >> 4) * 16;
    const uint32_t bBase = sb + STAGE_A + (wn*32 + ((lane >> 4) << 3) + (lane & 7)) * ROWB
                              + (((lane >> 3) & 1) * 16);

    float acc[4][4][4];
    #pragma unroll
    for (int i = 0; i < 4; i++)
        #pragma unroll
        for (int j = 0; j < 4; j++)
            #pragma unroll
            for (int r = 0; r < 4; r++) acc[i][j][r] = 0.0f;

    #pragma unroll
    for (int s = 0; s < NSTG-1; s++){
        #pragma unroll
        for (int q = 0; q < 3; q++)
            cpasync16(sb + s*STAGE_SZ + t_soff[q], t_gptr[q] + s*BK);
        cp_commit();
    }

    for (int kt = 0; kt < NKT; kt++){
        cp_wait<NSTG-2>();
        __syncthreads();

        int nkt = kt + NSTG - 1;
        if (nkt < NKT){
            uint32_t stb = sb + (nkt % NSTG)*STAGE_SZ;
            #pragma unroll
            for (int q = 0; q < 3; q++)
                cpasync16(stb + t_soff[q], t_gptr[q] + nkt*BK);
        }
        cp_commit();

        const uint32_t stage = (kt % NSTG) * STAGE_SZ;
        #pragma unroll
        for (int s = 0; s < 2; s++){
            uint32_t a[4][4], b[4][2];
            #pragma unroll
            for (int i = 0; i < 4; i++)
                ldsm4(aBase + stage + i*16*ROWB + s*32, a[i][0], a[i][1], a[i][2], a[i][3]);
            #pragma unroll
            for (int j2 = 0; j2 < 2; j2++){
                uint32_t r0, r1, r2, r3;
                ldsm4(bBase + stage + j2*16*ROWB + s*32, r0, r1, r2, r3);
                b[2*j2][0] = r0;   b[2*j2][1] = r1;
                b[2*j2+1][0] = r2; b[2*j2+1][1] = r3;
            }
            #pragma unroll
            for (int i = 0; i < 4; i++)
                #pragma unroll
                for (int j = 0; j < 4; j++)
                    mma16816(acc[i][j], a[i][0], a[i][1], a[i][2], a[i][3], b[j][0], b[j][1]);
        }
    }

    // epilogue
    const int colBase = blockN + wn*32 + 2*(lane & 3);
    float2 bj[4];
    #pragma unroll
    for (int j = 0; j < 4; j++) bj[j] = *(const float2*)(bias + colBase + j*8);

    #pragma unroll
    for (int i = 0; i < 4; i++){
        int row0 = blockM + wm*64 + i*16 + (lane >> 2);
        float* r0p = g_ts + (size_t)row0 * Nn + colBase;
        float* r1p = r0p + (size_t)8 * Nn;
        #pragma unroll
        for (int j = 0; j < 4; j++){
            float2 v0 = make_float2(acc[i][j][0] + bj[j].x, acc[i][j][1] + bj[j].y);
            float2 v1 = make_float2(acc[i][j][2] + bj[j].x, acc[i][j][3] + bj[j].y);
            *(float2*)(r0p + j*8) = v0;
            *(float2*)(r1p + j*8) = v1;
        }
    }
}

// ---------------- 4. max-sum scan: compacted rows, runtime trip count ----------------
struct ScanState {
    float hid[7];
    float sc;
};

__device__ __forceinline__ void scan_load(float2* buf, const float2* base, int chunk){
    #pragma unroll
    for (int u = 0; u < 4; u++){
        const float2* q = base + (size_t)(chunk*4 + u) * (Nn/2);
        #pragma unroll
        for (int j = 0; j < 7; j++) buf[u*7 + j] = q[j];
    }
}

__device__ __forceinline__ void scan_step(ScanState& st, const float* f,
                                          const float* eps, bool end5){
    float ae[7];
    ae[0] = st.hid[0];
    #pragma unroll
    for (int m = 1; m < 7; m++) ae[m] = fmaxf(st.hid[m], st.hid[m-1] + eps[m-1]);
    float nh[7];
    nh[0] = fmaxf(0.0f, ae[0] + f[0]);
    #pragma unroll
    for (int m = 1; m < 7; m++)
        nh[m] = fmaxf(ae[m-1] + f[7 + m - 1], ae[m] + f[m]);
    #pragma unroll
    for (int m = 0; m < 7; m++) st.hid[m] = nh[m];
    st.sc = fmaxf(st.sc, end5 ? st.hid[5] : st.hid[6]);
}

__device__ __forceinline__ void scan_compute(ScanState& st, const float2* buf,
                                             const float* eps, bool end5){
    #pragma unroll
    for (int u = 0; u < 4; u++){
        float f[14];
        #pragma unroll
        for (int j = 0; j < 7; j++){ f[2*j] = buf[u*7 + j].x; f[2*j+1] = buf[u*7 + j].y; }
        scan_step(st, f, eps, end5);
    }
}

__global__ __launch_bounds__(64) void scan_kernel(const int* __restrict__ doc_lens,
                                                  const float* __restrict__ epsilons)
{
    int idx = blockIdx.x * 64 + threadIdx.x;
    int b = idx >> 9;
    int p = idx & 511;

    float eps[6];
    #pragma unroll
    for (int i = 0; i < 6; i++) eps[i] = epsilons[p*6 + i];
    const bool end5 = (p < 256);
    const int dl = doc_lens[b];
    const int n4 = dl >> 2, rem = dl & 3;

    ScanState st;
    st.hid[0] = 0.0f;
    #pragma unroll
    for (int m = 1; m < 7; m++) st.hid[m] = NEGV;
    st.sc = NEGV;

    const float2* base = (const float2*)(g_ts + (size_t)g_off[b] * Nn + (size_t)p * 14);

    float2 buf0[28], buf1[28];
    scan_load(buf0, base, 0);

    int c = 0;
    #pragma unroll 1
    while (c + 2 <= n4){
        scan_load(buf1, base, c + 1);
        scan_compute(st, buf0, eps, end5);
        if (c + 2 < n4) scan_load(buf0, base, c + 2);
        scan_compute(st, buf1, eps, end5);
        c += 2;
    }
    if (c < n4){
        scan_compute(st, buf0, eps, end5);
    }
    #pragma unroll 1
    for (int u = 0; u < rem; u++){
        const float2* q = base + (size_t)(n4*4 + u) * (Nn/2);
        float f[14];
        #pragma unroll
        for (int j = 0; j < 7; j++){ float2 v = q[j]; f[2*j] = v.x; f[2*j+1] = v.y; }
        scan_step(st, f, eps, end5);
    }
    g_scores[idx] = st.sc;
}

// ---------------- 5. batchnorm + binarize + final linear ----------------
__global__ __launch_bounds__(512) void final_kernel(const float* __restrict__ bn_w,
                                                    const float* __restrict__ bn_b,
                                                    const float* __restrict__ fw,
                                                    const float* __restrict__ fb,
                                                    float* __restrict__ out)
{
    __shared__ unsigned char sbin[Bb][Pp];
    int p = threadIdx.x;

    float x[Bb];
    float s = 0.0f;
    #pragma unroll
    for (int b = 0; b < Bb; b++){ x[b] = g_scores[b*Pp + p]; s += x[b]; }
    float mean = s * (1.0f / Bb);
    float v = 0.0f;
    #pragma unroll
    for (int b = 0; b < Bb; b++){ float d = x[b] - mean; v += d * d; }
    v *= (1.0f / Bb);
    float inv = rsqrtf(v + 1e-5f);
    float w = bn_w[p], bb = bn_b[p];
    #pragma unroll
    for (int b = 0; b < Bb; b++){
        float y = (x[b] - mean) * inv * w + bb;
        sbin[b][p] = (y > 0.0f) ? 1 : 0;
    }
    __syncthreads();

    int warp = p >> 5, lane = p & 31;
    #pragma unroll
    for (int q = 0; q < 4; q++){
        int o = warp * 4 + q;
        int b = o >> 1, c = o & 1;
        float acc = 0.0f;
        for (int pp = lane; pp < Pp; pp += 32)
            if (sbin[b][pp]) acc += fw[c*Pp + pp];
        #pragma unroll
        for (int off = 16; off > 0; off >>= 1)
            acc += __shfl_xor_sync(0xffffffffu, acc, off);
        if (lane == 0) out[b*NCc + c] = acc + fb[c];
    }
}

// ---------------- host launch ----------------
extern "C" void kernel_launch(void* const* d_in, const int* in_sizes, int n_in,
                              void* d_out, int out_size)
{
    const int*   tokens    = (const int*)  d_in[0];
    const int*   doc_lens  = (const int*)  d_in[1];
    const float* emb_table = (const float*)d_in[2];
    const float* diags     = (const float*)d_in[3];
    const float* bias      = (const float*)d_in[4];
    const float* epsilons  = (const float*)d_in[5];
    const float* bn_weight = (const float*)d_in[6];
    const float* bn_bias   = (const float*)d_in[7];
    const float* final_w   = (const float*)d_in[8];
    const float* final_b   = (const float*)d_in[9];
    float* out = (float*)d_out;

    offsets_kernel<<<1, 32>>>(doc_lens);
    convA_kernel<<<Mm, 128>>>(tokens, emb_table, doc_lens);
    convB_kernel<<<Nn, 128>>>(diags);

    cudaFuncSetAttribute(gemm_kernel, cudaFuncAttributeMaxDynamicSharedMemorySize, SMEM_GEMM);
    dim3 grid(Nn / TILE_N, Mm / TILE_M);   // (28, 32); M-tiles beyond padTo exit
    gemm_kernel<<<grid, 512, SMEM_GEMM>>>(bias);

    scan_kernel<<<(Bb*Pp) / 64, 64>>>(doc_lens, epsilons);
    final_kernel<<<1, 512>>>(bn_weight, bn_bias, final_w, final_b, out);
}

// round 8
// speedup vs baseline: 1.6144x; 1.0511x over previous
#include <cuda_runtime.h>
#include <cuda_bf16.h>
#include <cstdint>

// ---------------- problem constants ----------------
#define Bb    32
#define Tt    128
#define Pp    512
#define MAXL  7
#define Dd    300
#define KSEG  304            // per-segment K (>=300, mult of 16)
#define KP    (4*KSEG)       // 1216 = 19*64
#define Nn    7168           // P*ND*MAXL
#define Mm    4096           // B*T (max)
#define NCc   2
#define NEGV  (-1e30f)

// gemm tiling: CTA 128(M) x 256(N), 8 warps (2M x 4N), warp tile 64x64, BK=64
#define TILE_M 128
#define TILE_N 256
#define BK    64
#define NKT   (KP/BK)        // 19
#define NSTG  3
#define ROWB  144            // 128 B data + 16 pad -> conflict-free ldmatrix
#define STAGE_A   (TILE_M*ROWB)          // 18432
#define STAGE_B   (TILE_N*ROWB)          // 36864
#define STAGE_SZ  (STAGE_A+STAGE_B)      // 55296
#define SMEM_GEMM (NSTG*STAGE_SZ)        // 165888

// ---------------- scratch ----------------
__device__ __nv_bfloat16 g_Aq[(size_t)Mm * KP];   // [h,h,m,m], M-compacted
__device__ __nv_bfloat16 g_Bq[(size_t)Nn * KP];   // [h,m,h,m]
__device__ float g_ts[(size_t)Mm * Nn];           // M-compacted
__device__ float g_scores[Bb * Pp];
__device__ int   g_off[Bb + 1];
__device__ int   g_padTo;

// ---------------- PTX helpers ----------------
__device__ __forceinline__ void cpasync16(uint32_t s, const void* g){
    asm volatile("cp.async.cg.shared.global [%0], [%1], 16;" :: "r"(s), "l"(g));
}
__device__ __forceinline__ void cp_commit(){
    asm volatile("cp.async.commit_group;" ::: "memory");
}
template<int N> __device__ __forceinline__ void cp_wait(){
    asm volatile("cp.async.wait_group %0;" :: "n"(N) : "memory");
}
__device__ __forceinline__ void ldsm4(uint32_t a, uint32_t& r0, uint32_t& r1, uint32_t& r2, uint32_t& r3){
    asm volatile("ldmatrix.sync.aligned.m8n8.x4.shared.b16 {%0,%1,%2,%3}, [%4];"
                 : "=r"(r0), "=r"(r1), "=r"(r2), "=r"(r3) : "r"(a));
}
__device__ __forceinline__ void mma16816(float* c, uint32_t a0, uint32_t a1, uint32_t a2, uint32_t a3,
                                         uint32_t b0, uint32_t b1){
    asm volatile("mma.sync.aligned.m16n8k16.row.col.f32.bf16.bf16.f32 "
                 "{%0,%1,%2,%3}, {%4,%5,%6,%7}, {%8,%9}, {%0,%1,%2,%3};"
                 : "+f"(c[0]), "+f"(c[1]), "+f"(c[2]), "+f"(c[3])
                 : "r"(a0), "r"(a1), "r"(a2), "r"(a3), "r"(b0), "r"(b1));
}

// ---------------- 0. doc-length prefix offsets ----------------
__global__ void offsets_kernel(const int* __restrict__ doc_lens){
    if (threadIdx.x == 0){
        int acc = 0;
        for (int b = 0; b < Bb; b++){ g_off[b] = acc; acc += doc_lens[b]; }
        g_off[Bb] = acc;
        g_padTo = (acc + TILE_M - 1) & ~(TILE_M - 1);
    }
}

// ---------------- 1/2. bf16 split-precision conversion ----------------
__global__ void convA_kernel(const int* __restrict__ tokens, const float* __restrict__ emb,
                             const int* __restrict__ doc_lens){
    int b = blockIdx.x >> 7, t = blockIdx.x & 127;
    if (t >= doc_lens[b]) return;
    int mrow = g_off[b] + t;
    int tok = tokens[blockIdx.x];
    __nv_bfloat16* row = g_Aq + (size_t)mrow * KP;
    const float* src = emb + (size_t)tok * Dd;
    for (int k = threadIdx.x; k < KSEG; k += blockDim.x){
        float x = (k < Dd) ? src[k] : 0.0f;
        __nv_bfloat16 h = __float2bfloat16(x);
        __nv_bfloat16 m = __float2bfloat16(x - __bfloat162float(h));
        row[0*KSEG + k] = h;  row[1*KSEG + k] = h;
        row[2*KSEG + k] = m;  row[3*KSEG + k] = m;
    }
}
__global__ void convB_kernel(const float* __restrict__ diags){
    int n = blockIdx.x;
    __nv_bfloat16* row = g_Bq + (size_t)n * KP;
    const float* src = diags + (size_t)n * Dd;
    for (int k = threadIdx.x; k < KSEG; k += blockDim.x){
        float x = (k < Dd) ? src[k] : 0.0f;
        __nv_bfloat16 h = __float2bfloat16(x);
        __nv_bfloat16 m = __float2bfloat16(x - __bfloat162float(h));
        row[0*KSEG + k] = h;  row[1*KSEG + k] = m;
        row[2*KSEG + k] = h;  row[3*KSEG + k] = m;
    }
}

// ---------------- 3. bf16 mma.sync GEMM: 256 thr, warp 64x64, BK=64, frag double-buffer ----------------
#define CPT 12   // cp.async tasks per thread per stage: 384 rows x 8 chunks / 256 thr

__global__ __launch_bounds__(256, 1) void gemm_kernel(const float* __restrict__ bias)
{
    const int blockM = blockIdx.y * TILE_M;
    if (blockM >= g_padTo) return;

    extern __shared__ char smem[];
    const uint32_t sb = (uint32_t)__cvta_generic_to_shared(smem);
    const int tid = threadIdx.x;
    const int lane = tid & 31, wid = tid >> 5;
    const int wm = wid & 1, wn = wid >> 1;     // 2M x 4N
    const int blockN = blockIdx.x * TILE_N;

    const __nv_bfloat16* gA = g_Aq + (size_t)blockM * KP;
    const __nv_bfloat16* gB = g_Bq + (size_t)blockN * KP;

    // cp.async tasks: 384 rows x 8 x 16B chunks
    uint32_t t_soff[CPT];
    const __nv_bfloat16* t_gptr[CPT];
    #pragma unroll
    for (int q = 0; q < CPT; q++){
        int id = tid + q*256;                  // 0..3071
        int row = id >> 3, ch = id & 7;
        int isB = (row >= TILE_M);
        int r2  = isB ? (row - TILE_M) : row;
        t_soff[q] = (isB ? STAGE_A : 0) + r2*ROWB + ch*16;
        t_gptr[q] = (isB ? gB : gA) + (size_t)r2 * KP + ch*8;
    }

    // ldmatrix bases
    const uint32_t aBase = sb + (wm*64 + (lane & 15)) * ROWB + (lane >> 4) * 16;
    const uint32_t bBase = sb + STAGE_A + (wn*64 + ((lane >> 4) << 3) + (lane & 7)) * ROWB
                              + (((lane >> 3) & 1) * 16);

    float acc[4][8][4];
    #pragma unroll
    for (int i = 0; i < 4; i++)
        #pragma unroll
        for (int j = 0; j < 8; j++)
            #pragma unroll
            for (int r = 0; r < 4; r++) acc[i][j][r] = 0.0f;

    // prologue: issue NSTG-1 = 2 stages
    #pragma unroll
    for (int s = 0; s < NSTG-1; s++){
        #pragma unroll
        for (int q = 0; q < CPT; q++)
            cpasync16(sb + s*STAGE_SZ + t_soff[q], t_gptr[q] + s*BK);
        cp_commit();
    }

    uint32_t a[2][4][4], b[2][8][2];

    for (int kt = 0; kt < NKT; kt++){
        cp_wait<NSTG-2>();
        __syncthreads();
        const uint32_t stage = (kt % NSTG) * STAGE_SZ;

        // load s=0 fragments into buffer 0
        #pragma unroll
        for (int i = 0; i < 4; i++)
            ldsm4(aBase + stage + i*16*ROWB, a[0][i][0], a[0][i][1], a[0][i][2], a[0][i][3]);
        #pragma unroll
        for (int j2 = 0; j2 < 4; j2++){
            uint32_t r0, r1, r2, r3;
            ldsm4(bBase + stage + j2*16*ROWB, r0, r1, r2, r3);
            b[0][2*j2][0] = r0;   b[0][2*j2][1] = r1;
            b[0][2*j2+1][0] = r2; b[0][2*j2+1][1] = r3;
        }

        // issue next stage's cp.async
        int nkt = kt + NSTG - 1;
        if (nkt < NKT){
            uint32_t stb = sb + (nkt % NSTG)*STAGE_SZ;
            #pragma unroll
            for (int q = 0; q < CPT; q++)
                cpasync16(stb + t_soff[q], t_gptr[q] + nkt*BK);
        }
        cp_commit();

        // 4 k-steps of 16, double-buffered fragments
        #pragma unroll
        for (int s = 0; s < 4; s++){
            const int cur = s & 1, nxt = cur ^ 1;
            if (s < 3){
                #pragma unroll
                for (int i = 0; i < 4; i++)
                    ldsm4(aBase + stage + i*16*ROWB + (s+1)*32,
                          a[nxt][i][0], a[nxt][i][1], a[nxt][i][2], a[nxt][i][3]);
                #pragma unroll
                for (int j2 = 0; j2 < 4; j2++){
                    uint32_t r0, r1, r2, r3;
                    ldsm4(bBase + stage + j2*16*ROWB + (s+1)*32, r0, r1, r2, r3);
                    b[nxt][2*j2][0] = r0;   b[nxt][2*j2][1] = r1;
                    b[nxt][2*j2+1][0] = r2; b[nxt][2*j2+1][1] = r3;
                }
            }
            #pragma unroll
            for (int i = 0; i < 4; i++)
                #pragma unroll
                for (int j = 0; j < 8; j++)
                    mma16816(acc[i][j], a[cur][i][0], a[cur][i][1], a[cur][i][2], a[cur][i][3],
                             b[cur][j][0], b[cur][j][1]);
        }
    }

    // epilogue: add bias, store float2 pairs
    const int colBase = blockN + wn*64 + 2*(lane & 3);
    #pragma unroll
    for (int i = 0; i < 4; i++){
        int row0 = blockM + wm*64 + i*16 + (lane >> 2);
        float* r0p = g_ts + (size_t)row0 * Nn + colBase;
        float* r1p = r0p + (size_t)8 * Nn;
        #pragma unroll
        for (int j = 0; j < 8; j++){
            float2 bj = *(const float2*)(bias + colBase + j*8);
            float2 v0 = make_float2(acc[i][j][0] + bj.x, acc[i][j][1] + bj.y);
            float2 v1 = make_float2(acc[i][j][2] + bj.x, acc[i][j][3] + bj.y);
            *(float2*)(r0p + j*8) = v0;
            *(float2*)(r1p + j*8) = v1;
        }
    }
}

// ---------------- 4. max-sum scan: compacted rows, runtime trip count ----------------
struct ScanState {
    float hid[7];
    float sc;
};

__device__ __forceinline__ void scan_load(float2* buf, const float2* base, int chunk){
    #pragma unroll
    for (int u = 0; u < 4; u++){
        const float2* q = base + (size_t)(chunk*4 + u) * (Nn/2);
        #pragma unroll
        for (int j = 0; j < 7; j++) buf[u*7 + j] = q[j];
    }
}

__device__ __forceinline__ void scan_step(ScanState& st, const float* f,
                                          const float* eps, bool end5){
    float ae[7];
    ae[0] = st.hid[0];
    #pragma unroll
    for (int m = 1; m < 7; m++) ae[m] = fmaxf(st.hid[m], st.hid[m-1] + eps[m-1]);
    float nh[7];
    nh[0] = fmaxf(0.0f, ae[0] + f[0]);
    #pragma unroll
    for (int m = 1; m < 7; m++)
        nh[m] = fmaxf(ae[m-1] + f[7 + m - 1], ae[m] + f[m]);
    #pragma unroll
    for (int m = 0; m < 7; m++) st.hid[m] = nh[m];
    st.sc = fmaxf(st.sc, end5 ? st.hid[5] : st.hid[6]);
}

__device__ __forceinline__ void scan_compute(ScanState& st, const float2* buf,
                                             const float* eps, bool end5){
    #pragma unroll
    for (int u = 0; u < 4; u++){
        float f[14];
        #pragma unroll
        for (int j = 0; j < 7; j++){ f[2*j] = buf[u*7 + j].x; f[2*j+1] = buf[u*7 + j].y; }
        scan_step(st, f, eps, end5);
    }
}

__global__ __launch_bounds__(64) void scan_kernel(const int* __restrict__ doc_lens,
                                                  const float* __restrict__ epsilons)
{
    int idx = blockIdx.x * 64 + threadIdx.x;
    int b = idx >> 9;
    int p = idx & 511;

    float eps[6];
    #pragma unroll
    for (int i = 0; i < 6; i++) eps[i] = epsilons[p*6 + i];
    const bool end5 = (p < 256);
    const int dl = doc_lens[b];
    const int n4 = dl >> 2, rem = dl & 3;

    ScanState st;
    st.hid[0] = 0.0f;
    #pragma unroll
    for (int m = 1; m < 7; m++) st.hid[m] = NEGV;
    st.sc = NEGV;

    const float2* base = (const float2*)(g_ts + (size_t)g_off[b] * Nn + (size_t)p * 14);

    float2 buf0[28], buf1[28];
    scan_load(buf0, base, 0);

    int c = 0;
    #pragma unroll 1
    while (c + 2 <= n4){
        scan_load(buf1, base, c + 1);
        scan_compute(st, buf0, eps, end5);
        if (c + 2 < n4) scan_load(buf0, base, c + 2);
        scan_compute(st, buf1, eps, end5);
        c += 2;
    }
    if (c < n4){
        scan_compute(st, buf0, eps, end5);
    }
    #pragma unroll 1
    for (int u = 0; u < rem; u++){
        const float2* q = base + (size_t)(n4*4 + u) * (Nn/2);
        float f[14];
        #pragma unroll
        for (int j = 0; j < 7; j++){ float2 v = q[j]; f[2*j] = v.x; f[2*j+1] = v.y; }
        scan_step(st, f, eps, end5);
    }
    g_scores[idx] = st.sc;
}

// ---------------- 5. batchnorm + binarize + final linear ----------------
__global__ __launch_bounds__(512) void final_kernel(const float* __restrict__ bn_w,
                                                    const float* __restrict__ bn_b,
                                                    const float* __restrict__ fw,
                                                    const float* __restrict__ fb,
                                                    float* __restrict__ out)
{
    __shared__ unsigned char sbin[Bb][Pp];
    int p = threadIdx.x;

    float x[Bb];
    float s = 0.0f;
    #pragma unroll
    for (int b = 0; b < Bb; b++){ x[b] = g_scores[b*Pp + p]; s += x[b]; }
    float mean = s * (1.0f / Bb);
    float v = 0.0f;
    #pragma unroll
    for (int b = 0; b < Bb; b++){ float d = x[b] - mean; v += d * d; }
    v *= (1.0f / Bb);
    float inv = rsqrtf(v + 1e-5f);
    float w = bn_w[p], bb = bn_b[p];
    #pragma unroll
    for (int b = 0; b < Bb; b++){
        float y = (x[b] - mean) * inv * w + bb;
        sbin[b][p] = (y > 0.0f) ? 1 : 0;
    }
    __syncthreads();

    int warp = p >> 5, lane = p & 31;
    #pragma unroll
    for (int q = 0; q < 4; q++){
        int o = warp * 4 + q;
        int b = o >> 1, c = o & 1;
        float acc = 0.0f;
        for (int pp = lane; pp < Pp; pp += 32)
            if (sbin[b][pp]) acc += fw[c*Pp + pp];
        #pragma unroll
        for (int off = 16; off > 0; off >>= 1)
            acc += __shfl_xor_sync(0xffffffffu, acc, off);
        if (lane == 0) out[b*NCc + c] = acc + fb[c];
    }
}

// ---------------- host launch ----------------
extern "C" void kernel_launch(void* const* d_in, const int* in_sizes, int n_in,
                              void* d_out, int out_size)
{
    const int*   tokens    = (const int*)  d_in[0];
    const int*   doc_lens  = (const int*)  d_in[1];
    const float* emb_table = (const float*)d_in[2];
    const float* diags     = (const float*)d_in[3];
    const float* bias      = (const float*)d_in[4];
    const float* epsilons  = (const float*)d_in[5];
    const float* bn_weight = (const float*)d_in[6];
    const float* bn_bias   = (const float*)d_in[7];
    const float* final_w   = (const float*)d_in[8];
    const float* final_b   = (const float*)d_in[9];
    float* out = (float*)d_out;

    offsets_kernel<<<1, 32>>>(doc_lens);
    convA_kernel<<<Mm, 128>>>(tokens, emb_table, doc_lens);
    convB_kernel<<<Nn, 128>>>(diags);

    cudaFuncSetAttribute(gemm_kernel, cudaFuncAttributeMaxDynamicSharedMemorySize, SMEM_GEMM);
    dim3 grid(Nn / TILE_N, Mm / TILE_M);   // (28, 32); M-tiles beyond padTo exit
    gemm_kernel<<<grid, 256, SMEM_GEMM>>>(bias);

    scan_kernel<<<(Bb*Pp) / 64, 64>>>(doc_lens, epsilons);
    final_kernel<<<1, 512>>>(bn_weight, bn_bias, final_w, final_b, out);
}